// round 5
// baseline (speedup 1.0000x reference)
#include <cuda_runtime.h>
#include <cuda_fp16.h>
#include <math.h>

#define NN 50000
#define EE 1600000
#define DD 128
#define HC 64     // H*C = 2*32
#define NB 196    // ceil(NN/256) scan blocks

// ---- scratch (device globals; no allocation allowed) ----
__device__ float   g_h[NN * HC];        // h = elu(x) @ W  fp32     12.8 MB
__device__ __half  g_hh[NN * HC];       // fp16 mirror of h          6.4 MB
__device__ float   g_asrc[NN * 2];
__device__ float   g_adst[NN * 2];
__device__ float2  g_nwcnt[NN];         // {sum w, count} per source node
__device__ int     g_deg[NN];           // in-degree (excl self loop)
__device__ int     g_off[NN];           // exclusive prefix of deg
__device__ int     g_cursor[NN];        // scatter cursors
__device__ int     g_bsum[256];
__device__ int     g_bsumx[256];
__device__ float4  g_sorted[EE];        // {src(asint), e0, e1, pad}  25.6 MB

__device__ __forceinline__ float lrelu(float a) { return a > 0.0f ? a : 0.2f * a; }
__device__ __forceinline__ float elu_f(float v) { return v > 0.0f ? v : (__expf(v) - 1.0f); }

__device__ __forceinline__ void fma4(float4& acc, const float4 wv, const float xs) {
    acc.x += xs * wv.x; acc.y += xs * wv.y; acc.z += xs * wv.z; acc.w += xs * wv.w;
}

// ---------------- 1) h = elu(x) @ W  (W staged in smem; elu fused; fp16 mirror out) ----------------
__global__ void k_gemm(const float* __restrict__ x, const float* __restrict__ W) {
    __shared__ float sW[DD * HC];                 // 32 KB
    int tid = threadIdx.x;                        // 256 threads
    const float4* Wv = (const float4*)W;
    float4* sWv = (float4*)sW;
#pragma unroll
    for (int i = 0; i < 8; i++) sWv[tid + i * 256] = Wv[tid + i * 256];
    __syncthreads();

    int r  = tid >> 2;                            // 64 rows / block
    int cg = (tid & 3) << 4;                      // 16 cols / thread
    int gr = blockIdx.x * 64 + r;
    if (gr >= NN) return;

    float4 a0 = make_float4(0,0,0,0), a1 = a0, a2 = a0, a3 = a0;
    const float4* xp = (const float4*)(x + (size_t)gr * DD);
#pragma unroll 4
    for (int k4 = 0; k4 < 32; k4++) {
        float4 xv = xp[k4];
        xv.x = elu_f(xv.x); xv.y = elu_f(xv.y); xv.z = elu_f(xv.z); xv.w = elu_f(xv.w);
#pragma unroll
        for (int j = 0; j < 4; j++) {
            float xs = (j == 0) ? xv.x : (j == 1) ? xv.y : (j == 2) ? xv.z : xv.w;
            const float4* wr = (const float4*)&sW[(k4 * 4 + j) * HC + cg];
            fma4(a0, wr[0], xs);
            fma4(a1, wr[1], xs);
            fma4(a2, wr[2], xs);
            fma4(a3, wr[3], xs);
        }
    }
    float4* op = (float4*)(g_h + (size_t)gr * HC + cg);
    op[0] = a0; op[1] = a1; op[2] = a2; op[3] = a3;

    // fp16 mirror: 16 halves = 8 half2 = 32B
    __half2* hp = (__half2*)(g_hh + (size_t)gr * HC + cg);
    hp[0] = __floats2half2_rn(a0.x, a0.y);
    hp[1] = __floats2half2_rn(a0.z, a0.w);
    hp[2] = __floats2half2_rn(a1.x, a1.y);
    hp[3] = __floats2half2_rn(a1.z, a1.w);
    hp[4] = __floats2half2_rn(a2.x, a2.y);
    hp[5] = __floats2half2_rn(a2.z, a2.w);
    hp[6] = __floats2half2_rn(a3.x, a3.y);
    hp[7] = __floats2half2_rn(a3.z, a3.w);
}

// ---------------- 2) per-node (one warp/node): a_src, a_dst; zero counters ----------------
__global__ void k_node_prep(const float* __restrict__ att_src, const float* __restrict__ att_dst) {
    int warp_in_block = threadIdx.x >> 5;
    int lane = threadIdx.x & 31;
    int n = blockIdx.x * 8 + warp_in_block;
    if (n >= NN) return;

    float h0 = g_h[(size_t)n * HC + lane];
    float h1 = g_h[(size_t)n * HC + 32 + lane];
    float as0 = h0 * att_src[lane];
    float ad0 = h0 * att_dst[lane];
    float as1 = h1 * att_src[32 + lane];
    float ad1 = h1 * att_dst[32 + lane];
#pragma unroll
    for (int off = 16; off >= 1; off >>= 1) {
        as0 += __shfl_xor_sync(0xffffffff, as0, off);
        ad0 += __shfl_xor_sync(0xffffffff, ad0, off);
        as1 += __shfl_xor_sync(0xffffffff, as1, off);
        ad1 += __shfl_xor_sync(0xffffffff, ad1, off);
    }
    if (lane == 0) {
        g_asrc[2*n] = as0; g_asrc[2*n+1] = as1;
        g_adst[2*n] = ad0; g_adst[2*n+1] = ad1;
        g_nwcnt[n] = make_float2(0.0f, 0.0f);
        g_deg[n] = 0;
    }
}

// ---------------- 3) histogram: deg[dst]++, nwcnt[src] += {w,1} ----------------
__global__ void k_hist(const int* __restrict__ ei, const float* __restrict__ wgt) {
    int e = blockIdx.x * blockDim.x + threadIdx.x;
    if (e >= EE) return;
    int s = __ldg(&ei[e]);
    int d = __ldg(&ei[EE + e]);
    atomicAdd(&g_deg[d], 1);
    float w = __ldg(&wgt[e]);
    asm volatile("red.global.add.v2.f32 [%0], {%1,%2};"
                 :: "l"((float*)(g_nwcnt + s)), "f"(w), "f"(1.0f) : "memory");
}

// ---------------- 4) three-step exclusive scan of deg -> off ----------------
__global__ void k_scan1() {
    __shared__ int tmp[256];
    int tid = threadIdx.x;
    int i = blockIdx.x * 256 + tid;
    int v = (i < NN) ? g_deg[i] : 0;
    tmp[tid] = v;
    __syncthreads();
#pragma unroll
    for (int off = 1; off < 256; off <<= 1) {
        int t = (tid >= off) ? tmp[tid - off] : 0;
        __syncthreads();
        tmp[tid] += t;
        __syncthreads();
    }
    if (i < NN) g_off[i] = tmp[tid] - v;
    if (tid == 255) g_bsum[blockIdx.x] = tmp[255];
}
__global__ void k_scan2() {
    __shared__ int tmp[256];
    int tid = threadIdx.x;
    int v = (tid < NB) ? g_bsum[tid] : 0;
    tmp[tid] = v;
    __syncthreads();
#pragma unroll
    for (int off = 1; off < 256; off <<= 1) {
        int t = (tid >= off) ? tmp[tid - off] : 0;
        __syncthreads();
        tmp[tid] += t;
        __syncthreads();
    }
    if (tid < NB) g_bsumx[tid] = tmp[tid] - v;
}
__global__ void k_scan3() {
    int i = blockIdx.x * 256 + threadIdx.x;
    if (i >= NN) return;
    int o = g_off[i] + g_bsumx[blockIdx.x];
    g_off[i] = o;
    g_cursor[i] = o;
}

// ---------------- 5) scatter: packed {src, e0, e1} records sorted by dst ----------------
__global__ void k_scatter(const int* __restrict__ ei) {
    int e = blockIdx.x * blockDim.x + threadIdx.x;
    if (e >= EE) return;
    int s = __ldg(&ei[e]);
    int d = __ldg(&ei[EE + e]);
    float2 as = *(const float2*)(g_asrc + 2 * s);
    float2 ad = *(const float2*)(g_adst + 2 * d);
    float e0 = __expf(lrelu(as.x + ad.x));
    float e1 = __expf(lrelu(as.y + ad.y));
    int pos = atomicAdd(&g_cursor[d], 1);
    g_sorted[pos] = make_float4(__int_as_float(s), e0, e1, 0.0f);
}

// ---------------- 6) gather: one warp per dst, fp16 h, unroll-4 batched loads ----------------
__global__ void k_gather(float* __restrict__ out, const float* __restrict__ bias,
                         const float* __restrict__ esc) {
    int warp_in_block = threadIdx.x >> 5;
    int lane = threadIdx.x & 31;
    int n = blockIdx.x * 8 + warp_in_block;
    if (n >= NN) return;

    int head = lane >> 4;                 // lanes 0-15: head0, 16-31: head1
    int start = g_off[n];
    int cnt   = g_deg[n];

    float2 acc = make_float2(0.0f, 0.0f);
    float den = 0.0f;
    const __half2* hh = (const __half2*)g_hh;

    int j = 0;
    for (; j + 4 <= cnt; j += 4) {
        float4 r0 = __ldg(&g_sorted[start + j]);
        float4 r1 = __ldg(&g_sorted[start + j + 1]);
        float4 r2 = __ldg(&g_sorted[start + j + 2]);
        float4 r3 = __ldg(&g_sorted[start + j + 3]);
        __half2 v0 = __ldg(hh + (size_t)__float_as_int(r0.x) * 32 + lane);
        __half2 v1 = __ldg(hh + (size_t)__float_as_int(r1.x) * 32 + lane);
        __half2 v2 = __ldg(hh + (size_t)__float_as_int(r2.x) * 32 + lane);
        __half2 v3 = __ldg(hh + (size_t)__float_as_int(r3.x) * 32 + lane);
        float ee0 = head ? r0.z : r0.y;
        float ee1 = head ? r1.z : r1.y;
        float ee2 = head ? r2.z : r2.y;
        float ee3 = head ? r3.z : r3.y;
        float2 f0 = __half22float2(v0);
        float2 f1 = __half22float2(v1);
        float2 f2 = __half22float2(v2);
        float2 f3 = __half22float2(v3);
        acc.x += ee0 * f0.x + ee1 * f1.x + ee2 * f2.x + ee3 * f3.x;
        acc.y += ee0 * f0.y + ee1 * f1.y + ee2 * f2.y + ee3 * f3.y;
        den   += (ee0 + ee1) + (ee2 + ee3);
    }
    for (; j < cnt; j++) {
        float4 r0 = __ldg(&g_sorted[start + j]);
        __half2 v0 = __ldg(hh + (size_t)__float_as_int(r0.x) * 32 + lane);
        float ee0 = head ? r0.z : r0.y;
        float2 f0 = __half22float2(v0);
        acc.x += ee0 * f0.x; acc.y += ee0 * f0.y;
        den += ee0;
    }

    // self loop (fp32 h)
    float a_self = lrelu(g_asrc[2*n + head] + g_adst[2*n + head]);
    float e_self = __expf(a_self);
    float2 hs = *(const float2*)(g_h + (size_t)n * HC + 2 * lane);
    acc.x += e_self * hs.x; acc.y += e_self * hs.y;
    den += e_self;

    float rd = __frcp_rn(den);

    float2 nwc = g_nwcnt[n];
    float nw = nwc.x / fmaxf(nwc.y, 1.0f);
    nw = fminf(fmaxf(nw, 0.2f), 5.0f);
    float sf  = 0.1f / (1.0f + __expf(-esc[0]));
    float add = sf * (nw - 1.0f);

    float2 b2 = *(const float2*)(bias + 2 * lane);
    float2 o;
    o.x = acc.x * rd + b2.x + add;
    o.y = acc.y * rd + b2.y + add;
    *(float2*)(out + (size_t)n * HC + 2 * lane) = o;
}

extern "C" void kernel_launch(void* const* d_in, const int* in_sizes, int n_in,
                              void* d_out, int out_size) {
    const float* x       = (const float*)d_in[0];
    const int*   ei      = (const int*)  d_in[1];
    const float* wgt     = (const float*)d_in[2];
    const float* W       = (const float*)d_in[3];
    const float* att_src = (const float*)d_in[4];
    const float* att_dst = (const float*)d_in[5];
    const float* bias    = (const float*)d_in[6];
    const float* esc     = (const float*)d_in[7];
    float* out = (float*)d_out;
    (void)in_sizes; (void)n_in; (void)out_size;

    k_gemm      <<<(NN + 63) / 64,       256>>>(x, W);
    k_node_prep <<<(NN + 7) / 8,         256>>>(att_src, att_dst);
    k_hist      <<<(EE + 255) / 256,     256>>>(ei, wgt);
    k_scan1     <<<NB,                   256>>>();
    k_scan2     <<<1,                    256>>>();
    k_scan3     <<<NB,                   256>>>();
    k_scatter   <<<(EE + 255) / 256,     256>>>(ei);
    k_gather    <<<(NN + 7) / 8,         256>>>(out, bias, esc);
}

// round 6
// speedup vs baseline: 1.5043x; 1.5043x over previous
#include <cuda_runtime.h>
#include <cuda_fp16.h>
#include <math.h>

#define NN 50000
#define EE 1600000
#define DD 128
#define HC 64     // H*C = 2*32
#define NB 196    // ceil(NN/256) scan blocks

// ---- scratch (device globals; no allocation allowed) ----
__device__ __half  g_hh[NN * HC];       // fp16 h = elu(x) @ W      6.4 MB
__device__ float   g_asrc[NN * 2];
__device__ float   g_adst[NN * 2];
__device__ float2  g_nwcnt[NN];         // {sum w, count} per source node
__device__ int     g_deg[NN];           // in-degree (excl self loop)
__device__ int     g_off[NN];           // block-local exclusive scan (pre scan3)
__device__ int     g_cursor[NN];        // scatter cursors (post scatter = end)
__device__ int     g_bsum[256];
__device__ int     g_bsumx[256];
__device__ float4  g_sorted[EE];        // {src(asint), e0, e1, pad}  25.6 MB

__device__ __forceinline__ float lrelu(float a) { return a > 0.0f ? a : 0.2f * a; }
__device__ __forceinline__ float elu_f(float v) { return v > 0.0f ? v : (__expf(v) - 1.0f); }

__device__ __forceinline__ void fma4(float4& acc, const float4 wv, const float xs) {
    acc.x += xs * wv.x; acc.y += xs * wv.y; acc.z += xs * wv.z; acc.w += xs * wv.w;
}
__device__ __forceinline__ float dot4(const float4 a, const float4 b) {
    return a.x*b.x + a.y*b.y + a.z*b.z + a.w*b.w;
}

// ---------------- 1) h = elu(x) @ W, register-blocked 4x8, fused attention dots ----------------
__global__ void k_gemm(const float* __restrict__ x, const float* __restrict__ W,
                       const float* __restrict__ att_src, const float* __restrict__ att_dst) {
    __shared__ float sW[DD * HC];                 // 32 KB
    __shared__ float sAs[HC], sAd[HC];
    int tid = threadIdx.x;                        // 256 threads
    const float4* Wv = (const float4*)W;
    float4* sWv = (float4*)sW;
#pragma unroll
    for (int i = 0; i < 8; i++) sWv[tid + i * 256] = Wv[tid + i * 256];
    if (tid < HC) { sAs[tid] = att_src[tid]; sAd[tid] = att_dst[tid]; }
    __syncthreads();

    int cg = tid & 7;                             // 8 cols starting at cg*8
    int rg = tid >> 3;                            // 0..31, 4 rows each
    int rb = blockIdx.x * 128 + rg * 4;           // first row of this thread

    float4 a[4][2];
#pragma unroll
    for (int i = 0; i < 4; i++) { a[i][0] = make_float4(0,0,0,0); a[i][1] = make_float4(0,0,0,0); }

    const float4* xp[4];
#pragma unroll
    for (int i = 0; i < 4; i++) {
        int r = rb + i; if (r >= NN) r = NN - 1;  // clamp (stores predicated later)
        xp[i] = (const float4*)(x + (size_t)r * DD);
    }

#pragma unroll 2
    for (int k4 = 0; k4 < 32; k4++) {
        float4 xv[4];
#pragma unroll
        for (int i = 0; i < 4; i++) {
            float4 v = __ldg(&xp[i][k4]);
            v.x = elu_f(v.x); v.y = elu_f(v.y); v.z = elu_f(v.z); v.w = elu_f(v.w);
            xv[i] = v;
        }
#pragma unroll
        for (int j = 0; j < 4; j++) {
            const float4* wr = (const float4*)&sW[(k4 * 4 + j) * HC + cg * 8];
            float4 w0 = wr[0], w1 = wr[1];
#pragma unroll
            for (int i = 0; i < 4; i++) {
                float xs = (j == 0) ? xv[i].x : (j == 1) ? xv[i].y : (j == 2) ? xv[i].z : xv[i].w;
                fma4(a[i][0], w0, xs);
                fma4(a[i][1], w1, xs);
            }
        }
    }

    // attention dot partials over this thread's 8 cols
    float4 s0 = ((const float4*)sAs)[cg * 2], s1 = ((const float4*)sAs)[cg * 2 + 1];
    float4 d0 = ((const float4*)sAd)[cg * 2], d1 = ((const float4*)sAd)[cg * 2 + 1];
    float asp[4], adp[4];
#pragma unroll
    for (int i = 0; i < 4; i++) {
        asp[i] = dot4(a[i][0], s0) + dot4(a[i][1], s1);
        adp[i] = dot4(a[i][0], d0) + dot4(a[i][1], d1);
    }
    // reduce across the 4 lanes of each head group (cg 0-3 = head0, cg 4-7 = head1)
#pragma unroll
    for (int off = 1; off <= 2; off <<= 1) {
#pragma unroll
        for (int i = 0; i < 4; i++) {
            asp[i] += __shfl_xor_sync(0xffffffff, asp[i], off);
            adp[i] += __shfl_xor_sync(0xffffffff, adp[i], off);
        }
    }
    if ((cg & 3) == 0) {
        int head = cg >> 2;
#pragma unroll
        for (int i = 0; i < 4; i++) {
            int r = rb + i;
            if (r < NN) {
                g_asrc[2*r + head] = asp[i];
                g_adst[2*r + head] = adp[i];
                if (head == 0) { g_nwcnt[r] = make_float2(0.0f, 0.0f); g_deg[r] = 0; }
            }
        }
    }

    // fp16 h store: 4 rows x 8 cols
#pragma unroll
    for (int i = 0; i < 4; i++) {
        int r = rb + i;
        if (r < NN) {
            __half2* hp = (__half2*)(g_hh + (size_t)r * HC + cg * 8);
            hp[0] = __floats2half2_rn(a[i][0].x, a[i][0].y);
            hp[1] = __floats2half2_rn(a[i][0].z, a[i][0].w);
            hp[2] = __floats2half2_rn(a[i][1].x, a[i][1].y);
            hp[3] = __floats2half2_rn(a[i][1].z, a[i][1].w);
        }
    }
}

// ---------------- 2) histogram: deg[dst]++, nwcnt[src] += {w,1} ----------------
__global__ void k_hist(const int* __restrict__ ei, const float* __restrict__ wgt) {
    int e = blockIdx.x * blockDim.x + threadIdx.x;
    if (e >= EE) return;
    int s = __ldg(&ei[e]);
    int d = __ldg(&ei[EE + e]);
    atomicAdd(&g_deg[d], 1);
    float w = __ldg(&wgt[e]);
    asm volatile("red.global.add.v2.f32 [%0], {%1,%2};"
                 :: "l"((float*)(g_nwcnt + s)), "f"(w), "f"(1.0f) : "memory");
}

// ---------------- 3) shuffle-based 3-step exclusive scan ----------------
__global__ void k_scan1() {
    int tid = threadIdx.x, lane = tid & 31, w = tid >> 5;
    int i = blockIdx.x * 256 + tid;
    int v = (i < NN) ? g_deg[i] : 0;
    int s = v;
#pragma unroll
    for (int off = 1; off < 32; off <<= 1) {
        int t = __shfl_up_sync(0xffffffff, s, off);
        if (lane >= off) s += t;
    }
    __shared__ int ws[8];
    if (lane == 31) ws[w] = s;
    __syncthreads();
    int woff = 0;
#pragma unroll
    for (int k = 0; k < 8; k++) woff += (k < w) ? ws[k] : 0;
    if (i < NN) g_off[i] = s - v + woff;
    if (tid == 255) g_bsum[blockIdx.x] = s + woff;
}
__global__ void k_scan2() {
    int tid = threadIdx.x, lane = tid & 31, w = tid >> 5;
    int v = (tid < NB) ? g_bsum[tid] : 0;
    int s = v;
#pragma unroll
    for (int off = 1; off < 32; off <<= 1) {
        int t = __shfl_up_sync(0xffffffff, s, off);
        if (lane >= off) s += t;
    }
    __shared__ int ws[8];
    if (lane == 31) ws[w] = s;
    __syncthreads();
    int woff = 0;
#pragma unroll
    for (int k = 0; k < 8; k++) woff += (k < w) ? ws[k] : 0;
    g_bsumx[tid] = s - v + woff;
}
__global__ void k_scan3() {
    int i = blockIdx.x * 256 + threadIdx.x;
    if (i >= NN) return;
    g_cursor[i] = g_off[i] + g_bsumx[blockIdx.x];
}

// ---------------- 4) scatter: packed {src, e0, e1} records sorted by dst ----------------
__global__ void k_scatter(const int* __restrict__ ei) {
    int e = blockIdx.x * blockDim.x + threadIdx.x;
    if (e >= EE) return;
    int s = __ldg(&ei[e]);
    int d = __ldg(&ei[EE + e]);
    float2 as = *(const float2*)(g_asrc + 2 * s);
    float2 ad = *(const float2*)(g_adst + 2 * d);
    float e0 = __expf(lrelu(as.x + ad.x));
    float e1 = __expf(lrelu(as.y + ad.y));
    int pos = atomicAdd(&g_cursor[d], 1);
    g_sorted[pos] = make_float4(__int_as_float(s), e0, e1, 0.0f);
}

// ---------------- 5) gather: one warp per dst, software-pipelined, fused epilogue ----------------
__global__ void k_gather(float* __restrict__ out, const float* __restrict__ bias,
                         const float* __restrict__ esc) {
    int warp_in_block = threadIdx.x >> 5;
    int lane = threadIdx.x & 31;
    int n = blockIdx.x * 8 + warp_in_block;
    if (n >= NN) return;

    int head = lane >> 4;                 // lanes 0-15: head0, 16-31: head1
    int cnt   = g_deg[n];
    int start = g_cursor[n] - cnt;        // cursor is end-of-segment after scatter

    float2 acc = make_float2(0.0f, 0.0f);
    float den = 0.0f;
    const __half2* hh = (const __half2*)g_hh;
    const float4* rec = g_sorted + start;

    int nq = cnt >> 2, rem = cnt & 3;
    float4 r0, r1, r2, r3;
    if (nq) { r0 = __ldg(rec); r1 = __ldg(rec + 1); r2 = __ldg(rec + 2); r3 = __ldg(rec + 3); }
    for (int q = 0; q < nq; q++) {
        __half2 v0 = __ldg(hh + (size_t)__float_as_int(r0.x) * 32 + lane);
        __half2 v1 = __ldg(hh + (size_t)__float_as_int(r1.x) * 32 + lane);
        __half2 v2 = __ldg(hh + (size_t)__float_as_int(r2.x) * 32 + lane);
        __half2 v3 = __ldg(hh + (size_t)__float_as_int(r3.x) * 32 + lane);
        float e0 = head ? r0.z : r0.y;
        float e1 = head ? r1.z : r1.y;
        float e2 = head ? r2.z : r2.y;
        float e3 = head ? r3.z : r3.y;
        bool more = (q + 1 < nq);
        float4 n0, n1, n2, n3;
        if (more) {
            const float4* p = rec + 4 * (q + 1);
            n0 = __ldg(p); n1 = __ldg(p + 1); n2 = __ldg(p + 2); n3 = __ldg(p + 3);
        }
        float2 f0 = __half22float2(v0);
        float2 f1 = __half22float2(v1);
        float2 f2 = __half22float2(v2);
        float2 f3 = __half22float2(v3);
        acc.x += e0 * f0.x + e1 * f1.x + e2 * f2.x + e3 * f3.x;
        acc.y += e0 * f0.y + e1 * f1.y + e2 * f2.y + e3 * f3.y;
        den   += (e0 + e1) + (e2 + e3);
        if (more) { r0 = n0; r1 = n1; r2 = n2; r3 = n3; }
    }
    const float4* tp = rec + nq * 4;
    for (int t = 0; t < rem; t++) {
        float4 r = __ldg(tp + t);
        __half2 v = __ldg(hh + (size_t)__float_as_int(r.x) * 32 + lane);
        float e0 = head ? r.z : r.y;
        float2 f = __half22float2(v);
        acc.x += e0 * f.x; acc.y += e0 * f.y;
        den += e0;
    }

    // self loop
    float a_self = lrelu(g_asrc[2*n + head] + g_adst[2*n + head]);
    float e_self = __expf(a_self);
    float2 hs = __half22float2(__ldg(hh + (size_t)n * 32 + lane));
    acc.x += e_self * hs.x; acc.y += e_self * hs.y;
    den += e_self;

    float rd = __frcp_rn(den);

    float2 nwc = g_nwcnt[n];
    float nw = nwc.x / fmaxf(nwc.y, 1.0f);
    nw = fminf(fmaxf(nw, 0.2f), 5.0f);
    float sf  = 0.1f / (1.0f + __expf(-esc[0]));
    float add = sf * (nw - 1.0f);

    float2 b2 = *(const float2*)(bias + 2 * lane);
    float2 o;
    o.x = acc.x * rd + b2.x + add;
    o.y = acc.y * rd + b2.y + add;
    *(float2*)(out + (size_t)n * HC + 2 * lane) = o;
}

extern "C" void kernel_launch(void* const* d_in, const int* in_sizes, int n_in,
                              void* d_out, int out_size) {
    const float* x       = (const float*)d_in[0];
    const int*   ei      = (const int*)  d_in[1];
    const float* wgt     = (const float*)d_in[2];
    const float* W       = (const float*)d_in[3];
    const float* att_src = (const float*)d_in[4];
    const float* att_dst = (const float*)d_in[5];
    const float* bias    = (const float*)d_in[6];
    const float* esc     = (const float*)d_in[7];
    float* out = (float*)d_out;
    (void)in_sizes; (void)n_in; (void)out_size;

    k_gemm      <<<(NN + 127) / 128,     256>>>(x, W, att_src, att_dst);
    k_hist      <<<(EE + 255) / 256,     256>>>(ei, wgt);
    k_scan1     <<<NB,                   256>>>();
    k_scan2     <<<1,                    256>>>();
    k_scan3     <<<NB,                   256>>>();
    k_scatter   <<<(EE + 255) / 256,     256>>>(ei);
    k_gather    <<<(NN + 7) / 8,         256>>>(out, bias, esc);
}